// round 14
// baseline (speedup 1.0000x reference)
#include <cuda_runtime.h>
#include <cuda_fp16.h>
#include <cstdint>

#define N_IN   200000
#define N_OUT  400000
#define K3     27
#define MP     100000
#define C      128
#define EPS    1e-5f

#define TILE_M 128
#define NTHR   256
#define NTILES 782                           // ceil(MP/128)
#define TASKS  (K3 * NTILES)                 // 21114
#define TPB    72
#define GRID_MAIN ((TASKS + TPB - 1) / TPB)  // 294
#define GRID_BN  592                         // 4 CTAs/SM x 148 — all co-resident

// bn work-stealing: n4 = 400000*32 = 12,800,000 float4; 500 chunks of 25600
#define BN_N4   ((size_t)N_OUT * (C / 4))
#define BN_CH   25600
#define BN_NCH  500

// ---------------------------------------------------------------------------
// persistent device scratch (allocations are forbidden)
// ---------------------------------------------------------------------------
__device__ float g_sum[C];
__device__ float g_sumsq[C];
__device__ unsigned int g_bar;               // grid-barrier counter
__device__ unsigned int g_c1;                // phase-1 chunk counter
__device__ unsigned int g_c2;                // phase-2 chunk counter

__device__ __half g_fh[(size_t)N_IN * C];      // feats, fp16
__device__ __half g_wt[(size_t)K3 * C * C];    // W^T: [k][n(c_out)][c_in], fp16

// ---------------------------------------------------------------------------
// helpers
// ---------------------------------------------------------------------------
__device__ __forceinline__ uint32_t smem_u32(const void* p) {
    uint32_t a;
    asm("{ .reg .u64 t; cvta.to.shared.u64 t, %1; cvt.u32.u64 %0, t; }"
        : "=r"(a) : "l"(p));
    return a;
}
__device__ __forceinline__ void red_v4(float* p, float a, float b, float c, float d) {
    asm volatile("red.global.add.v4.f32 [%0], {%1, %2, %3, %4};"
                 :: "l"(p), "f"(a), "f"(b), "f"(c), "f"(d) : "memory");
}
__device__ __forceinline__ void ldsm_x4(uint32_t& r0, uint32_t& r1,
                                        uint32_t& r2, uint32_t& r3, uint32_t addr) {
    asm volatile("ldmatrix.sync.aligned.m8n8.x4.shared.b16 {%0,%1,%2,%3}, [%4];"
                 : "=r"(r0), "=r"(r1), "=r"(r2), "=r"(r3) : "r"(addr));
}
__device__ __forceinline__ void mma16816(float* c, uint32_t a0, uint32_t a1,
                                         uint32_t a2, uint32_t a3,
                                         uint32_t b0, uint32_t b1) {
    asm volatile(
        "mma.sync.aligned.m16n8k16.row.col.f32.f16.f16.f32 "
        "{%0,%1,%2,%3}, {%4,%5,%6,%7}, {%8,%9}, {%0,%1,%2,%3};"
        : "+f"(c[0]), "+f"(c[1]), "+f"(c[2]), "+f"(c[3])
        : "r"(a0), "r"(a1), "r"(a2), "r"(a3), "r"(b0), "r"(b1));
}
__device__ __forceinline__ void cp16(uint32_t dst, const void* src) {
    asm volatile("cp.async.cg.shared.global [%0], [%1], 16;"
                 :: "r"(dst), "l"(src) : "memory");
}
__device__ __forceinline__ void cp16z(uint32_t dst, const void* src, int nbytes) {
    asm volatile("cp.async.ca.shared.global [%0], [%1], 16, %2;"
                 :: "r"(dst), "l"(src), "r"(nbytes) : "memory");
}
#define CP_COMMIT()  asm volatile("cp.async.commit_group;" ::: "memory")
#define CP_WAIT(N)   asm volatile("cp.async.wait_group %0;" :: "n"(N) : "memory")

__device__ __forceinline__ void sts_v2(uint32_t addr, float a, float b) {
    asm volatile("st.shared.v2.f32 [%0], {%1, %2};" :: "r"(addr), "f"(a), "f"(b));
}
__device__ __forceinline__ float4 lds_v4(uint32_t addr) {
    float4 v;
    asm volatile("ld.shared.v4.f32 {%0,%1,%2,%3}, [%4];"
                 : "=f"(v.x), "=f"(v.y), "=f"(v.z), "=f"(v.w) : "r"(addr));
    return v;
}

// ---------------------------------------------------------------------------
// kernel 1: fused prep — coalesced W^T (blocks 0..431), zero out, feats->fp16,
//           reset stats + counters
// ---------------------------------------------------------------------------
__global__ void prep_kernel(float* __restrict__ out,
                            const float* __restrict__ feats,
                            const float* __restrict__ W) {
    __shared__ float tile[32][33];

    // blocks 0..431: one coalesced 32x32 W-transpose tile each (27*16 = 432)
    if (blockIdx.x < K3 * 16) {
        const int k   = blockIdx.x >> 4;
        const int rem = blockIdx.x & 15;
        const int n0  = (rem & 3) * 32;
        const int c0  = (rem >> 2) * 32;
        const int tx = threadIdx.x & 31, ty = threadIdx.x >> 5;  // 32 x 8

        const float* Wk = W + (size_t)k * C * C;
#pragma unroll
        for (int r = 0; r < 4; ++r)        // coalesced read: consecutive n
            tile[ty * 4 + r][tx] = Wk[(size_t)(c0 + ty * 4 + r) * C + n0 + tx];
        __syncthreads();

        __half* dst = g_wt + (size_t)k * C * C;
#pragma unroll
        for (int r = 0; r < 4; ++r) {      // coalesced write: consecutive c
            int n = n0 + ty * 4 + r;
            dst[(size_t)n * C + c0 + tx] = __float2half_rn(tile[tx][ty * 4 + r]);
        }
    }

    const size_t stride = (size_t)gridDim.x * blockDim.x;
    const size_t base = (size_t)blockIdx.x * blockDim.x + threadIdx.x;

    float4 z = make_float4(0.f, 0.f, 0.f, 0.f);
    for (size_t i = base; i < (size_t)N_OUT * (C / 4); i += stride)
        ((float4*)out)[i] = z;

    for (size_t i = base; i < (size_t)N_IN * (C / 4); i += stride) {
        float4 v = ((const float4*)feats)[i];
        __half h[4];
        h[0] = __float2half_rn(v.x);
        h[1] = __float2half_rn(v.y);
        h[2] = __float2half_rn(v.z);
        h[3] = __float2half_rn(v.w);
        ((uint2*)g_fh)[i] = *(uint2*)h;
    }

    if (blockIdx.x == gridDim.x - 1 && threadIdx.x < C) {
        g_sum[threadIdx.x]   = 0.f;
        g_sumsq[threadIdx.x] = 0.f;
        if (threadIdx.x == 0) { g_bar = 0u; g_c1 = 0u; g_c2 = 0u; }
    }
}

// ---------------------------------------------------------------------------
// kernel 2: persistent pipelined gather -> HMMA -> staged row-contig scatter
// ---------------------------------------------------------------------------
#define PAD_C   136
#define SM_MAPS 0                                 // 3 slots x 1024 B
#define SM_B    3072                              // 34816 B
#define SM_A0   (SM_B + C * PAD_C * 2)            // 37888
#define SM_A1   (SM_A0 + TILE_M * PAD_C * 2)      // 72704
#define SM_TOT  (SM_A1 + TILE_M * PAD_C * 2)      // 107520

__global__ void __launch_bounds__(NTHR, 2)
scatter_gemm(const int* __restrict__ in_maps,
             const int* __restrict__ out_maps,
             float*     __restrict__ out) {
    extern __shared__ char smem[];
    const uint32_t smb = smem_u32(smem);
    const int tid  = threadIdx.x;
    const int wid  = tid >> 5;
    const int lane = tid & 31;

    const int start = blockIdx.x * TPB;
    const int end   = min(start + TPB, TASKS);
    if (start >= end) return;

    const int wm = (wid & 3) * 32;
    const int wn = (wid >> 2) * 64;
    const uint32_t aOff = ((uint32_t)(wm + (lane & 15)) * PAD_C + ((lane >> 4) << 3)) * 2;
    const uint32_t bOff = ((uint32_t)(wn + ((lane >> 4) << 3) + (lane & 7)) * PAD_C
                          + (((lane >> 3) & 1) << 3)) * 2;

    auto issue_maps = [&](int j) {
        if (tid < 64) {
            const int kq = j / NTILES, tq = j - kq * NTILES;
            const bool isOm = tid >= 32;
            const int c16 = tid & 31;
            const int* src = (isOm ? out_maps : in_maps)
                           + (size_t)kq * MP + (size_t)tq * TILE_M + c16 * 4;
            int nb = min(TILE_M, MP - tq * TILE_M) * 4 - c16 * 16;
            nb = nb < 0 ? 0 : (nb > 16 ? 16 : nb);
            cp16z(smb + SM_MAPS + (uint32_t)(j % 3) * 1024 + (isOm ? 512u : 0u)
                      + (uint32_t)c16 * 16, src, nb);
        }
    };
    auto issue_gather = [&](int j, uint32_t abase) {
        const int* imn = (const int*)(smem + SM_MAPS + (j % 3) * 1024);
#pragma unroll
        for (int it = 0; it < 2048 / NTHR; ++it) {
            int idx = it * NTHR + tid;
            int row = idx >> 4, c8 = idx & 15;
            cp16(abase + (uint32_t)(row * PAD_C + c8 * 8) * 2,
                 g_fh + (size_t)imn[row] * C + c8 * 8);
        }
    };

    issue_maps(start);
    CP_COMMIT();
    CP_WAIT(0);
    __syncthreads();
    issue_gather(start, smb + SM_A0);
    if (start + 1 < end) issue_maps(start + 1);
    CP_COMMIT();

    int cur_k = -1;

    for (int i = start; i < end; ++i) {
        const int k = i / NTILES;
        const int t = i - k * NTILES;
        const int buf = i & 1;

        // B reload overlaps the cp.async wait (B is dead after the previous
        // tile's post-MMA barrier; its STS completes before the sync below)
        if (k != cur_k) {
            const uint4* bg = (const uint4*)(g_wt + (size_t)k * C * C);
#pragma unroll
            for (int it = 0; it < 2048 / NTHR; ++it) {
                int idx = it * NTHR + tid;
                int row = idx >> 4, c8 = idx & 15;
                *(uint4*)(smem + SM_B + (row * PAD_C + c8 * 8) * 2) = bg[idx];
            }
            cur_k = k;
        }

        CP_WAIT(0);            // A(i) + maps(i+1) landed
        __syncthreads();       // A/B visibility; protects reused buffers

        // prefetch next tile: A(i+1) + maps(i+2)
        if (i + 1 < end) {
            issue_gather(i + 1, smb + (buf ? SM_A0 : SM_A1));
            if (i + 2 < end) issue_maps(i + 2);
            CP_COMMIT();
        }

        const uint32_t aAddr = smb + (buf ? SM_A1 : SM_A0) + aOff;
        const uint32_t bAddr = smb + SM_B + bOff;

        float acc[2][8][4];
#pragma unroll
        for (int mb = 0; mb < 2; ++mb)
#pragma unroll
            for (int nbt = 0; nbt < 8; ++nbt)
#pragma unroll
                for (int j = 0; j < 4; ++j) acc[mb][nbt][j] = 0.f;

#pragma unroll
        for (int ks = 0; ks < 8; ++ks) {
            const uint32_t kb = ks * 32;
            uint32_t a[2][4];
#pragma unroll
            for (int mb = 0; mb < 2; ++mb)
                ldsm_x4(a[mb][0], a[mb][1], a[mb][2], a[mb][3],
                        aAddr + mb * (16 * PAD_C * 2) + kb);
            uint32_t b[4][4];
#pragma unroll
            for (int g = 0; g < 4; ++g)
                ldsm_x4(b[g][0], b[g][1], b[g][2], b[g][3],
                        bAddr + g * (16 * PAD_C * 2) + kb);
#pragma unroll
            for (int mb = 0; mb < 2; ++mb)
#pragma unroll
                for (int g = 0; g < 4; ++g) {
                    mma16816(acc[mb][2 * g],     a[mb][0], a[mb][1], a[mb][2], a[mb][3],
                             b[g][0], b[g][1]);
                    mma16816(acc[mb][2 * g + 1], a[mb][0], a[mb][1], a[mb][2], a[mb][3],
                             b[g][2], b[g][3]);
                }
        }

        __syncthreads();       // A[buf] dead for ALL warps -> staging

        const int* om = (const int*)(smem + SM_MAPS + (i % 3) * 1024) + 128;
        const int mvalid = min(TILE_M, MP - t * TILE_M);
        const uint32_t stage = smb + (buf ? SM_A1 : SM_A0) + (uint32_t)wid * 4096;

        const int rrA = lane >> 2;
        const int p   = lane & 3;
        const int jh  = p & 1;
        const int qr  = lane & 15;
        const int rhf = lane >> 4;

#pragma unroll
        for (int mb = 0; mb < 2; ++mb) {
#pragma unroll
            for (int nbt = 0; nbt < 8; ++nbt) {
                const int qi = nbt * 2 + (p >> 1);
                const uint32_t sw = (uint32_t)((qi ^ rrA) & 15);
                sts_v2(stage + (uint32_t)rrA * 256 + sw * 16 + (uint32_t)jh * 8,
                       acc[mb][nbt][0], acc[mb][nbt][1]);
                sts_v2(stage + (uint32_t)(rrA + 8) * 256 + sw * 16 + (uint32_t)jh * 8,
                       acc[mb][nbt][2], acc[mb][nbt][3]);
            }
            __syncwarp();
#pragma unroll
            for (int t8 = 0; t8 < 8; ++t8) {
                const int rr = t8 * 2 + rhf;
                float4 v = lds_v4(stage + (uint32_t)rr * 256
                                        + (uint32_t)((qr ^ (rr & 7)) & 15) * 16);
                const int grow = wm + mb * 16 + rr;
                if (grow < mvalid) {
                    float* dst = out + (size_t)om[grow] * C + wn + qr * 4;
                    red_v4(dst, v.x, v.y, v.z, v.w);
                }
            }
            __syncwarp();
        }
    }
}

// ---------------------------------------------------------------------------
// kernel 3: fused BN — work-stealing stats, grid barrier, work-stealing
//           reverse normalize (phase-2 chunks start at the L2-resident tail)
// ---------------------------------------------------------------------------
__global__ void __launch_bounds__(256, 4)
bn_fused(float* __restrict__ out,
         const float* __restrict__ gamma,
         const float* __restrict__ beta) {
    __shared__ float4 ssum[256];
    __shared__ float4 ssq[256];
    __shared__ float sc[C], sh[C];
    __shared__ unsigned int s_chunk;

    const int tid = threadIdx.x;
    const int c4  = tid & 31;

    // ---- phase 1: forward stats via chunk stealing ----
    float4 s = make_float4(0.f, 0.f, 0.f, 0.f);
    float4 q = make_float4(0.f, 0.f, 0.f, 0.f);
    const float4* o4 = (const float4*)out;
    for (;;) {
        if (tid == 0) s_chunk = atomicAdd(&g_c1, 1u);
        __syncthreads();
        unsigned int c = s_chunk;
        __syncthreads();
        if (c >= BN_NCH) break;
        const size_t base = (size_t)c * BN_CH;
#pragma unroll 4
        for (int j = tid; j < BN_CH; j += 256) {
            float4 v = o4[base + j];
            s.x += v.x; s.y += v.y; s.z += v.z; s.w += v.w;
            q.x += v.x * v.x; q.y += v.y * v.y;
            q.z += v.z * v.z; q.w += v.w * v.w;
        }
    }
    ssum[tid] = s;
    ssq[tid]  = q;
    __syncthreads();
#pragma unroll
    for (int st = 128; st >= 32; st >>= 1) {
        if (tid < st) {
            ssum[tid].x += ssum[tid + st].x; ssum[tid].y += ssum[tid + st].y;
            ssum[tid].z += ssum[tid + st].z; ssum[tid].w += ssum[tid + st].w;
            ssq[tid].x  += ssq[tid + st].x;  ssq[tid].y  += ssq[tid + st].y;
            ssq[tid].z  += ssq[tid + st].z;  ssq[tid].w  += ssq[tid + st].w;
        }
        __syncthreads();
    }
    if (tid < 32) {
        atomicAdd(&g_sum[c4 * 4 + 0], ssum[tid].x);
        atomicAdd(&g_sum[c4 * 4 + 1], ssum[tid].y);
        atomicAdd(&g_sum[c4 * 4 + 2], ssum[tid].z);
        atomicAdd(&g_sum[c4 * 4 + 3], ssum[tid].w);
        atomicAdd(&g_sumsq[c4 * 4 + 0], ssq[tid].x);
        atomicAdd(&g_sumsq[c4 * 4 + 1], ssq[tid].y);
        atomicAdd(&g_sumsq[c4 * 4 + 2], ssq[tid].z);
        atomicAdd(&g_sumsq[c4 * 4 + 3], ssq[tid].w);
    }

    // ---- device grid barrier (all GRID_BN CTAs co-resident) ----
    __syncthreads();
    if (tid == 0) {
        __threadfence();
        atomicAdd(&g_bar, 1u);
        while (atomicAdd(&g_bar, 0u) < (unsigned)gridDim.x) { }
        __threadfence();
    }
    __syncthreads();

    if (tid < C) {
        const float inv_n = 1.0f / (float)N_OUT;
        float mean = g_sum[tid] * inv_n;
        float var  = g_sumsq[tid] * inv_n - mean * mean;
        float scv  = rsqrtf(var + EPS) * gamma[tid];
        sc[tid] = scv;
        sh[tid] = beta[tid] - mean * scv;
    }
    __syncthreads();

    // ---- phase 2: reverse-order chunk stealing (tail chunks first) ----
    for (;;) {
        if (tid == 0) s_chunk = atomicAdd(&g_c2, 1u);
        __syncthreads();
        unsigned int c = s_chunk;
        __syncthreads();
        if (c >= BN_NCH) break;
        const size_t base = BN_N4 - (size_t)(c + 1) * BN_CH;
#pragma unroll 2
        for (int j = tid; j < BN_CH; j += 256) {
            const size_t i = base + j;
            int cc = (int)(i & 31);
            float4 v = ((float4*)out)[i];
            float4 ss = *(float4*)(sc + cc * 4);
            float4 hh = *(float4*)(sh + cc * 4);
            v.x = v.x * ss.x + hh.x;
            v.y = v.y * ss.y + hh.y;
            v.z = v.z * ss.z + hh.z;
            v.w = v.w * ss.w + hh.w;
            ((float4*)out)[i] = v;
        }
    }
}

// ---------------------------------------------------------------------------
// launch
// ---------------------------------------------------------------------------
extern "C" void kernel_launch(void* const* d_in, const int* in_sizes, int n_in,
                              void* d_out, int out_size) {
    const float* feats    = (const float*)d_in[0];
    const float* W        = (const float*)d_in[1];
    const float* gamma    = (const float*)d_in[2];
    const float* beta     = (const float*)d_in[3];
    const int*   in_maps  = (const int*)d_in[4];
    const int*   out_maps = (const int*)d_in[5];
    float* out = (float*)d_out;

    cudaFuncSetAttribute(scatter_gemm,
                         cudaFuncAttributeMaxDynamicSharedMemorySize, SM_TOT);

    prep_kernel<<<1184, 256>>>(out, feats, W);
    scatter_gemm<<<GRID_MAIN, NTHR, SM_TOT>>>(in_maps, out_maps, out);
    bn_fused<<<GRID_BN, 256>>>(out, gamma, beta);
}

// round 15
// speedup vs baseline: 1.0387x; 1.0387x over previous
#include <cuda_runtime.h>
#include <cuda_fp16.h>
#include <cstdint>

#define N_IN   200000
#define N_OUT  400000
#define K3     27
#define MP     100000
#define C      128
#define EPS    1e-5f

#define TILE_M 128
#define NTHR   256
#define NTILES 782                           // ceil(MP/128)
#define TASKS  (K3 * NTILES)                 // 21114
#define TPB    72
#define GRID_MAIN ((TASKS + TPB - 1) / TPB)  // 294
#define GRID_BN  592                         // 4 CTAs/SM x 148 — all co-resident

// ---------------------------------------------------------------------------
// persistent device scratch (allocations are forbidden)
// ---------------------------------------------------------------------------
__device__ float g_sum[C];
__device__ float g_sumsq[C];
__device__ unsigned int g_bar;               // grid-barrier counter

__device__ __half g_fh[(size_t)N_IN * C];      // feats, fp16
__device__ __half g_wt[(size_t)K3 * C * C];    // W^T: [k][n(c_out)][c_in], fp16

// ---------------------------------------------------------------------------
// helpers
// ---------------------------------------------------------------------------
__device__ __forceinline__ uint32_t smem_u32(const void* p) {
    uint32_t a;
    asm("{ .reg .u64 t; cvta.to.shared.u64 t, %1; cvt.u32.u64 %0, t; }"
        : "=r"(a) : "l"(p));
    return a;
}
__device__ __forceinline__ void red_v4(float* p, float a, float b, float c, float d) {
    asm volatile("red.global.add.v4.f32 [%0], {%1, %2, %3, %4};"
                 :: "l"(p), "f"(a), "f"(b), "f"(c), "f"(d) : "memory");
}
__device__ __forceinline__ void ldsm_x4(uint32_t& r0, uint32_t& r1,
                                        uint32_t& r2, uint32_t& r3, uint32_t addr) {
    asm volatile("ldmatrix.sync.aligned.m8n8.x4.shared.b16 {%0,%1,%2,%3}, [%4];"
                 : "=r"(r0), "=r"(r1), "=r"(r2), "=r"(r3) : "r"(addr));
}
__device__ __forceinline__ void mma16816(float* c, uint32_t a0, uint32_t a1,
                                         uint32_t a2, uint32_t a3,
                                         uint32_t b0, uint32_t b1) {
    asm volatile(
        "mma.sync.aligned.m16n8k16.row.col.f32.f16.f16.f32 "
        "{%0,%1,%2,%3}, {%4,%5,%6,%7}, {%8,%9}, {%0,%1,%2,%3};"
        : "+f"(c[0]), "+f"(c[1]), "+f"(c[2]), "+f"(c[3])
        : "r"(a0), "r"(a1), "r"(a2), "r"(a3), "r"(b0), "r"(b1));
}
__device__ __forceinline__ void cp16(uint32_t dst, const void* src) {
    asm volatile("cp.async.cg.shared.global [%0], [%1], 16;"
                 :: "r"(dst), "l"(src) : "memory");
}
__device__ __forceinline__ void cp16z(uint32_t dst, const void* src, int nbytes) {
    asm volatile("cp.async.ca.shared.global [%0], [%1], 16, %2;"
                 :: "r"(dst), "l"(src), "r"(nbytes) : "memory");
}
#define CP_COMMIT()  asm volatile("cp.async.commit_group;" ::: "memory")
#define CP_WAIT(N)   asm volatile("cp.async.wait_group %0;" :: "n"(N) : "memory")

__device__ __forceinline__ void sts_v2(uint32_t addr, float a, float b) {
    asm volatile("st.shared.v2.f32 [%0], {%1, %2};" :: "r"(addr), "f"(a), "f"(b));
}
__device__ __forceinline__ float4 lds_v4(uint32_t addr) {
    float4 v;
    asm volatile("ld.shared.v4.f32 {%0,%1,%2,%3}, [%4];"
                 : "=f"(v.x), "=f"(v.y), "=f"(v.z), "=f"(v.w) : "r"(addr));
    return v;
}

// ---------------------------------------------------------------------------
// kernel 1: fused prep — zero out + feats->fp16 in ONE loop (2 streams in
// flight), W transpose->fp16, reset stats + barrier
// ---------------------------------------------------------------------------
__global__ void prep_kernel(float* __restrict__ out,
                            const float* __restrict__ feats,
                            const float* __restrict__ W) {
    const size_t stride = (size_t)gridDim.x * blockDim.x;
    const size_t base = (size_t)blockIdx.x * blockDim.x + threadIdx.x;

    const size_t n_zero = (size_t)N_OUT * (C / 4);   // 12.8M float4
    const size_t n_ft   = (size_t)N_IN * (C / 4);    //  6.4M float4

    float4 z = make_float4(0.f, 0.f, 0.f, 0.f);
    for (size_t i = base; i < n_zero; i += stride) {
        ((float4*)out)[i] = z;                       // stream 1: zero store
        if (i < n_ft) {                              // stream 2: convert
            float4 v = ((const float4*)feats)[i];
            __half h[4];
            h[0] = __float2half_rn(v.x);
            h[1] = __float2half_rn(v.y);
            h[2] = __float2half_rn(v.z);
            h[3] = __float2half_rn(v.w);
            ((uint2*)g_fh)[i] = *(uint2*)h;
        }
    }

    for (size_t i = base; i < (size_t)K3 * C * C; i += stride) {
        int c  = (int)(i & (C - 1));
        int nn = (int)((i >> 7) & (C - 1));
        int k  = (int)(i >> 14);
        g_wt[i] = __float2half_rn(W[(size_t)k * C * C + (size_t)c * C + nn]);
    }

    if (blockIdx.x == 0 && threadIdx.x < C) {
        g_sum[threadIdx.x]   = 0.f;
        g_sumsq[threadIdx.x] = 0.f;
        if (threadIdx.x == 0) g_bar = 0u;     // reset grid barrier each replay
    }
}

// ---------------------------------------------------------------------------
// kernel 2: persistent pipelined gather -> HMMA -> staged row-contig scatter
// (byte-identical to the measured-best R6/R13 version)
// ---------------------------------------------------------------------------
#define PAD_C   136
#define SM_MAPS 0                                 // 3 slots x 1024 B
#define SM_B    3072                              // 34816 B
#define SM_A0   (SM_B + C * PAD_C * 2)            // 37888
#define SM_A1   (SM_A0 + TILE_M * PAD_C * 2)      // 72704
#define SM_TOT  (SM_A1 + TILE_M * PAD_C * 2)      // 107520

__global__ void __launch_bounds__(NTHR, 2)
scatter_gemm(const int* __restrict__ in_maps,
             const int* __restrict__ out_maps,
             float*     __restrict__ out) {
    extern __shared__ char smem[];
    const uint32_t smb = smem_u32(smem);
    const int tid  = threadIdx.x;
    const int wid  = tid >> 5;
    const int lane = tid & 31;

    const int start = blockIdx.x * TPB;
    const int end   = min(start + TPB, TASKS);
    if (start >= end) return;

    const int wm = (wid & 3) * 32;
    const int wn = (wid >> 2) * 64;
    const uint32_t aOff = ((uint32_t)(wm + (lane & 15)) * PAD_C + ((lane >> 4) << 3)) * 2;
    const uint32_t bOff = ((uint32_t)(wn + ((lane >> 4) << 3) + (lane & 7)) * PAD_C
                          + (((lane >> 3) & 1) << 3)) * 2;

    auto issue_maps = [&](int j) {
        if (tid < 64) {
            const int kq = j / NTILES, tq = j - kq * NTILES;
            const bool isOm = tid >= 32;
            const int c16 = tid & 31;
            const int* src = (isOm ? out_maps : in_maps)
                           + (size_t)kq * MP + (size_t)tq * TILE_M + c16 * 4;
            int nb = min(TILE_M, MP - tq * TILE_M) * 4 - c16 * 16;
            nb = nb < 0 ? 0 : (nb > 16 ? 16 : nb);
            cp16z(smb + SM_MAPS + (uint32_t)(j % 3) * 1024 + (isOm ? 512u : 0u)
                      + (uint32_t)c16 * 16, src, nb);
        }
    };
    auto issue_gather = [&](int j, uint32_t abase) {
        const int* imn = (const int*)(smem + SM_MAPS + (j % 3) * 1024);
#pragma unroll
        for (int it = 0; it < 2048 / NTHR; ++it) {
            int idx = it * NTHR + tid;
            int row = idx >> 4, c8 = idx & 15;
            cp16(abase + (uint32_t)(row * PAD_C + c8 * 8) * 2,
                 g_fh + (size_t)imn[row] * C + c8 * 8);
        }
    };

    issue_maps(start);
    CP_COMMIT();
    CP_WAIT(0);
    __syncthreads();
    issue_gather(start, smb + SM_A0);
    if (start + 1 < end) issue_maps(start + 1);
    CP_COMMIT();

    int cur_k = -1;

    for (int i = start; i < end; ++i) {
        const int k = i / NTILES;
        const int t = i - k * NTILES;
        const int buf = i & 1;

        CP_WAIT(0);
        __syncthreads();

        if (k != cur_k) {
            const uint4* bg = (const uint4*)(g_wt + (size_t)k * C * C);
#pragma unroll
            for (int it = 0; it < 2048 / NTHR; ++it) {
                int idx = it * NTHR + tid;
                int row = idx >> 4, c8 = idx & 15;
                *(uint4*)(smem + SM_B + (row * PAD_C + c8 * 8) * 2) = bg[idx];
            }
            cur_k = k;
            __syncthreads();
        }

        if (i + 1 < end) {
            issue_gather(i + 1, smb + (buf ? SM_A0 : SM_A1));
            if (i + 2 < end) issue_maps(i + 2);
            CP_COMMIT();
        }

        const uint32_t aAddr = smb + (buf ? SM_A1 : SM_A0) + aOff;
        const uint32_t bAddr = smb + SM_B + bOff;

        float acc[2][8][4];
#pragma unroll
        for (int mb = 0; mb < 2; ++mb)
#pragma unroll
            for (int nbt = 0; nbt < 8; ++nbt)
#pragma unroll
                for (int j = 0; j < 4; ++j) acc[mb][nbt][j] = 0.f;

#pragma unroll
        for (int ks = 0; ks < 8; ++ks) {
            const uint32_t kb = ks * 32;
            uint32_t a[2][4];
#pragma unroll
            for (int mb = 0; mb < 2; ++mb)
                ldsm_x4(a[mb][0], a[mb][1], a[mb][2], a[mb][3],
                        aAddr + mb * (16 * PAD_C * 2) + kb);
            uint32_t b[4][4];
#pragma unroll
            for (int g = 0; g < 4; ++g)
                ldsm_x4(b[g][0], b[g][1], b[g][2], b[g][3],
                        bAddr + g * (16 * PAD_C * 2) + kb);
#pragma unroll
            for (int mb = 0; mb < 2; ++mb)
#pragma unroll
                for (int g = 0; g < 4; ++g) {
                    mma16816(acc[mb][2 * g],     a[mb][0], a[mb][1], a[mb][2], a[mb][3],
                             b[g][0], b[g][1]);
                    mma16816(acc[mb][2 * g + 1], a[mb][0], a[mb][1], a[mb][2], a[mb][3],
                             b[g][2], b[g][3]);
                }
        }

        __syncthreads();

        const int* om = (const int*)(smem + SM_MAPS + (i % 3) * 1024) + 128;
        const int mvalid = min(TILE_M, MP - t * TILE_M);
        const uint32_t stage = smb + (buf ? SM_A1 : SM_A0) + (uint32_t)wid * 4096;

        const int rrA = lane >> 2;
        const int p   = lane & 3;
        const int jh  = p & 1;
        const int qr  = lane & 15;
        const int rhf = lane >> 4;

#pragma unroll
        for (int mb = 0; mb < 2; ++mb) {
#pragma unroll
            for (int nbt = 0; nbt < 8; ++nbt) {
                const int qi = nbt * 2 + (p >> 1);
                const uint32_t sw = (uint32_t)((qi ^ rrA) & 15);
                sts_v2(stage + (uint32_t)rrA * 256 + sw * 16 + (uint32_t)jh * 8,
                       acc[mb][nbt][0], acc[mb][nbt][1]);
                sts_v2(stage + (uint32_t)(rrA + 8) * 256 + sw * 16 + (uint32_t)jh * 8,
                       acc[mb][nbt][2], acc[mb][nbt][3]);
            }
            __syncwarp();
#pragma unroll
            for (int t8 = 0; t8 < 8; ++t8) {
                const int rr = t8 * 2 + rhf;
                float4 v = lds_v4(stage + (uint32_t)rr * 256
                                        + (uint32_t)((qr ^ (rr & 7)) & 15) * 16);
                const int grow = wm + mb * 16 + rr;
                if (grow < mvalid) {
                    float* dst = out + (size_t)om[grow] * C + wn + qr * 4;
                    red_v4(dst, v.x, v.y, v.z, v.w);
                }
            }
            __syncwarp();
        }
    }
}

// ---------------------------------------------------------------------------
// kernel 3: fused BN — forward stats, grid barrier (load-spin + backoff),
//           reverse normalize (static splits — proven fastest in R13)
// ---------------------------------------------------------------------------
__global__ void __launch_bounds__(256, 4)
bn_fused(float* __restrict__ out,
         const float* __restrict__ gamma,
         const float* __restrict__ beta) {
    __shared__ float4 ssum[256];
    __shared__ float4 ssq[256];
    __shared__ float sc[C], sh[C];

    const int tid = threadIdx.x;
    const int c4  = tid & 31;
    const size_t n4 = (size_t)N_OUT * (C / 4);
    const size_t stride = (size_t)gridDim.x * blockDim.x;   // multiple of 32

    // prefetch affine params before the barrier (independent)
    float gm = (tid < C) ? gamma[tid] : 0.f;
    float bt = (tid < C) ? beta[tid]  : 0.f;

    // ---- phase 1: forward stats (leaves tail of `out` resident in L2) ----
    float4 s = make_float4(0.f, 0.f, 0.f, 0.f);
    float4 q = make_float4(0.f, 0.f, 0.f, 0.f);
    const float4* o4 = (const float4*)out;
#pragma unroll 4
    for (size_t i = (size_t)blockIdx.x * blockDim.x + tid; i < n4; i += stride) {
        float4 v = o4[i];
        s.x += v.x; s.y += v.y; s.z += v.z; s.w += v.w;
        q.x += v.x * v.x; q.y += v.y * v.y; q.z += v.z * v.z; q.w += v.w * v.w;
    }
    ssum[tid] = s;
    ssq[tid]  = q;
    __syncthreads();
#pragma unroll
    for (int st = 128; st >= 32; st >>= 1) {
        if (tid < st) {
            ssum[tid].x += ssum[tid + st].x; ssum[tid].y += ssum[tid + st].y;
            ssum[tid].z += ssum[tid + st].z; ssum[tid].w += ssum[tid + st].w;
            ssq[tid].x  += ssq[tid + st].x;  ssq[tid].y  += ssq[tid + st].y;
            ssq[tid].z  += ssq[tid + st].z;  ssq[tid].w  += ssq[tid + st].w;
        }
        __syncthreads();
    }
    if (tid < 32) {
        atomicAdd(&g_sum[c4 * 4 + 0], ssum[tid].x);
        atomicAdd(&g_sum[c4 * 4 + 1], ssum[tid].y);
        atomicAdd(&g_sum[c4 * 4 + 2], ssum[tid].z);
        atomicAdd(&g_sum[c4 * 4 + 3], ssum[tid].w);
        atomicAdd(&g_sumsq[c4 * 4 + 0], ssq[tid].x);
        atomicAdd(&g_sumsq[c4 * 4 + 1], ssq[tid].y);
        atomicAdd(&g_sumsq[c4 * 4 + 2], ssq[tid].z);
        atomicAdd(&g_sumsq[c4 * 4 + 3], ssq[tid].w);
    }

    // ---- device grid barrier: atomic arrive, LOAD-spin with backoff ----
    __syncthreads();
    if (tid == 0) {
        __threadfence();                        // publish stats atomics
        atomicAdd(&g_bar, 1u);
        while (*(volatile unsigned int*)&g_bar < (unsigned)gridDim.x)
            __nanosleep(128);
        __threadfence();                        // acquire g_sum/g_sumsq
    }
    __syncthreads();

    // ---- fold stats into per-channel scale/shift ----
    if (tid < C) {
        const float inv_n = 1.0f / (float)N_OUT;
        float mean = g_sum[tid] * inv_n;
        float var  = g_sumsq[tid] * inv_n - mean * mean;
        float scv  = rsqrtf(var + EPS) * gm;
        sc[tid] = scv;
        sh[tid] = bt - mean * scv;
    }
    __syncthreads();

    // ---- phase 2: reverse normalize (hits L2-resident tail first) ----
    for (size_t j = (size_t)blockIdx.x * blockDim.x + tid; j < n4; j += stride) {
        const size_t i = n4 - 1 - j;
        int cc = (int)(i & 31);
        float4 v = ((float4*)out)[i];
        float4 ss = *(float4*)(sc + cc * 4);
        float4 hh = *(float4*)(sh + cc * 4);
        v.x = v.x * ss.x + hh.x;
        v.y = v.y * ss.y + hh.y;
        v.z = v.z * ss.z + hh.z;
        v.w = v.w * ss.w + hh.w;
        ((float4*)out)[i] = v;
    }
}

// ---------------------------------------------------------------------------
// launch
// ---------------------------------------------------------------------------
extern "C" void kernel_launch(void* const* d_in, const int* in_sizes, int n_in,
                              void* d_out, int out_size) {
    const float* feats    = (const float*)d_in[0];
    const float* W        = (const float*)d_in[1];
    const float* gamma    = (const float*)d_in[2];
    const float* beta     = (const float*)d_in[3];
    const int*   in_maps  = (const int*)d_in[4];
    const int*   out_maps = (const int*)d_in[5];
    float* out = (float*)d_out;

    cudaFuncSetAttribute(scatter_gemm,
                         cudaFuncAttributeMaxDynamicSharedMemorySize, SM_TOT);

    prep_kernel<<<1184, 256>>>(out, feats, W);
    scatter_gemm<<<GRID_MAIN, NTHR, SM_TOT>>>(in_maps, out_maps, out);
    bn_fused<<<GRID_BN, 256>>>(out, gamma, beta);
}